// round 9
// baseline (speedup 1.0000x reference)
#include <cuda_runtime.h>
#include <math.h>

#define HH 128
#define WW 128
#define NN 16384          // H*W
#define BB 2
#define DD 32
#define QQ 128
#define MM 16
#define EPSF 1e-8f

// ---------------- scratch (static device allocations; no cudaMalloc) --------
__device__ float g_feat1[BB*NN*DD];
__device__ float g_k   [BB*NN*DD];   // pre-normalized k-hat
__device__ float g_q   [BB*NN*DD];   // pre-normalized q-hat
__device__ float g_w   [BB*NN*25];   // unnormalized exp(cos) weights, [b][pixel][tap]
__device__ float g_hA  [BB*NN*QQ];
__device__ float g_hB  [BB*NN*QQ];

// ---------------- conv1: (B,H,W,3) -> relu -> (B,H,W,32) --------------------
__global__ void conv1_k(const float* __restrict__ x,
                        const float* __restrict__ w,
                        const float* __restrict__ bias) {
    __shared__ float sw[3*3*3*32];
    __shared__ float sb[32];
    for (int t = threadIdx.x; t < 864; t += 512) sw[t] = w[t];
    if (threadIdx.x < 32) sb[threadIdx.x] = bias[threadIdx.x];
    __syncthreads();

    int gid = blockIdx.x * 16 + (threadIdx.x >> 5);   // pixel in [0, B*N)
    int co  = threadIdx.x & 31;
    int b = gid >> 14, p = gid & (NN-1);
    int i = p >> 7, j = p & 127;

    float acc = sb[co];
    #pragma unroll
    for (int ky = 0; ky < 3; ky++) {
        int yi = i + ky - 1;
        if ((unsigned)yi >= HH) continue;
        #pragma unroll
        for (int kx = 0; kx < 3; kx++) {
            int xj = j + kx - 1;
            if ((unsigned)xj >= WW) continue;
            const float* xp = x + ((size_t)((b << 14) | (yi << 7) | xj)) * 3;
            const float* wp = sw + (ky*3 + kx) * 3 * 32;
            #pragma unroll
            for (int ci = 0; ci < 3; ci++) acc += xp[ci] * wp[ci*32 + co];
        }
    }
    g_feat1[(size_t)gid*32 + co] = fmaxf(acc, 0.f);
}

// ------- conv2 + fused k/q projection + normalization (k-hat, q-hat) --------
__global__ void conv2kq_k(const float* __restrict__ w,
                          const float* __restrict__ bias,
                          const float* __restrict__ wk,
                          const float* __restrict__ bk,
                          const float* __restrict__ wq) {
    __shared__ float sw[3*3*32*32];
    __shared__ float swk[1024], swq[1024];
    __shared__ float sb[32], sbk[32];
    for (int t = threadIdx.x; t < 9216; t += 512) sw[t] = w[t];
    for (int t = threadIdx.x; t < 1024; t += 512) { swk[t] = wk[t]; swq[t] = wq[t]; }
    if (threadIdx.x < 32) { sb[threadIdx.x] = bias[threadIdx.x]; sbk[threadIdx.x] = bk[threadIdx.x]; }
    __syncthreads();

    int gid = blockIdx.x * 16 + (threadIdx.x >> 5);
    int co  = threadIdx.x & 31;
    int b = gid >> 14, p = gid & (NN-1);
    int i = p >> 7, j = p & 127;

    float acc = sb[co];
    #pragma unroll
    for (int ky = 0; ky < 3; ky++) {
        int yi = i + ky - 1;
        if ((unsigned)yi >= HH) continue;
        #pragma unroll
        for (int kx = 0; kx < 3; kx++) {
            int xj = j + kx - 1;
            if ((unsigned)xj >= WW) continue;
            const float* fin = g_feat1 + ((size_t)((b << 14) | (yi << 7) | xj)) * 32;
            const float* wp  = sw + (ky*3 + kx) * 32 * 32;
            #pragma unroll
            for (int ci = 0; ci < 32; ci++) acc += fin[ci] * wp[ci*32 + co];
        }
    }
    float fv = fmaxf(acc, 0.f);          // feat2 value for channel co (stays in reg)

    float ka = sbk[co], qa = 0.f;
    #pragma unroll
    for (int ci = 0; ci < 32; ci++) {
        float f = __shfl_sync(0xffffffffu, fv, ci);
        ka += f * swk[ci*32 + co];
        qa += f * swq[ci*32 + co];
    }
    float ks = ka*ka, qs = qa*qa;
    #pragma unroll
    for (int o = 16; o; o >>= 1) {
        ks += __shfl_xor_sync(0xffffffffu, ks, o);
        qs += __shfl_xor_sync(0xffffffffu, qs, o);
    }
    // pre-normalize: cosine sim becomes a plain dot product downstream.
    float kinv = rsqrtf(fmaxf(ks, 1e-30f));
    float qinv = rsqrtf(fmaxf(qs, 1e-30f));
    g_k[(size_t)gid*32 + co] = ka * kinv;
    g_q[(size_t)gid*32 + co] = qa * qinv;
}

// ---------------- edge weights: exp(dot(q-hat, k-hat)), tile-based ----------
__global__ void edgew_k() {
    __shared__ float sk[32*145];    // [c][halo_pixel], padded stride
    __shared__ float sq[64*32];     // [tile_pixel][c]

    int b = blockIdx.z;
    int ti0 = blockIdx.y << 3, tj0 = blockIdx.x << 3;
    int tid = threadIdx.x;
    size_t bbase = (size_t)b << 14;

    // k halo: 144 pixels x 32 ch, transposed on the fly
    for (int t = tid; t < 1152; t += 256) {
        int hp = t >> 3, c4 = t & 7;
        int hr = hp / 12, hc = hp - hr*12;
        int gi = min(max(ti0 + hr - 2, 0), HH-1);
        int gj = min(max(tj0 + hc - 2, 0), WW-1);
        float4 v = ((const float4*)(g_k + (bbase + (gi << 7) + gj) * 32))[c4];
        sk[(c4*4+0)*145 + hp] = v.x;
        sk[(c4*4+1)*145 + hp] = v.y;
        sk[(c4*4+2)*145 + hp] = v.z;
        sk[(c4*4+3)*145 + hp] = v.w;
    }
    // q tile: 64 pixels x 32 ch, straight
    for (int t = tid; t < 512; t += 256) {
        int p = t >> 3, c4 = t & 7;
        int gi = ti0 + (p >> 3), gj = tj0 + (p & 7);
        ((float4*)sq)[t] = ((const float4*)(g_q + (bbase + (gi << 7) + gj) * 32))[c4];
    }
    __syncthreads();

    int lane = tid & 31, a = tid >> 5;          // warp = tile row a
    int d = min(lane, 24);
    int dr = d / 5, dc = d - dr*5;

    for (int cc = 0; cc < 8; cc++) {
        int p = a*8 + cc;
        int hidx = (a + dr)*12 + (cc + dc);
        const float* skp = sk + hidx;
        const float* sqp = sq + p*32;
        float s = 0.f;
        #pragma unroll
        for (int c = 0; c < 32; c++) s += sqp[c] * skp[c*145];
        if (lane < 25) {
            size_t gp = bbase + ((ti0 + a) << 7) + (tj0 + cc);
            g_w[gp*25 + lane] = __expf(s);
        }
    }
}

// ---------------- propagation: weighted 5x5 stencil + L2-normalize ----------
// 8x8 tile / block, 512 threads: warp = (tile column, channel-chunk) -- the
// two 64-ch chunks run in PARALLEL warps (TLP instead of per-warp ILP).
// Lane = channel pair. No halo smem, no pre-store barriers: warps read their
// 5x12 window straight from global (LDG.64, 256B coalesced, L1-served reuse).
// Weights pre-duplicated (w,w) in smem; inner loop per (output,row) =
// 2x LDS.128 + 1x LDS.64 + 5x fma.rn.f32x2. Cross-chunk L2-norm via a tiny
// smem reduction + one end barrier.
#define PROP_W_F2 (64*32)     // 64 ops x 32 float2 (row stride 6, padded)
__global__ __launch_bounds__(512, 3) void prop_k(const float* __restrict__ hinit, int it) {
    __shared__ float2 shw[PROP_W_F2];                // 16 KB
    __shared__ float sred[2][8][8];                  // [chunk][c][a] partial ss

    const float* hin = (it == 0) ? hinit : ((it & 1) ? g_hA : g_hB);
    float*       hout = (it & 1) ? g_hB : g_hA;

    int b = blockIdx.z;
    int ti0 = blockIdx.y << 3, tj0 = blockIdx.x << 3;
    int tid = threadIdx.x;
    int lane = tid & 31, w = tid >> 5;
    int c = w & 7, chunk = w >> 3;                   // 8 columns x 2 chunks

    const float* hb = hin + ((size_t)b << 21);       // b*N*128
    float* hob = hout + ((size_t)b << 21);

    // stage weights: (w,w) pairs; per-op row r at float2 offset op*32 + r*6
    const float* wb = g_w + ((size_t)b << 14) * 25;
    for (int t = tid; t < 1600; t += 512) {
        int op = t / 25, d = t - op*25;
        int a = op >> 3, cc = op & 7;
        int r = d / 5, cl = d - r*5;
        float ww = wb[(size_t)(((ti0 + a) << 7) | (tj0 + cc)) * 25 + d];
        shw[op*32 + r*6 + cl] = make_float2(ww, ww);
    }
    __syncthreads();

    const unsigned long long* shw64 = (const unsigned long long*)shw;

    unsigned long long acc[8];
    #pragma unroll
    for (int a = 0; a < 8; a++) acc[a] = 0ull;

    const float* hcb = hb + chunk*64 + 2*lane;       // this warp's channel pair
    #pragma unroll
    for (int hr = 0; hr < 12; hr++) {
        int gi = min(max(ti0 + hr - 2, 0), HH-1);
        const float* rowp = hcb + ((size_t)gi << 14);       // gi*128*128
        unsigned long long hv[5];
        #pragma unroll
        for (int dj = 0; dj < 5; dj++) {
            int gj = min(max(tj0 + c + dj - 2, 0), WW-1);
            hv[dj] = *(const unsigned long long*)(rowp + ((size_t)gj << 7));
        }
        #pragma unroll
        for (int a = 0; a < 8; a++) {
            if (a > hr || a + 4 < hr) continue;              // compile-time pruned
            const unsigned long long* wr = shw64 + (a*8 + c)*32 + (hr - a)*6;
            ulonglong2 p01 = *(const ulonglong2*)(wr);       // (w0,w0),(w1,w1)
            ulonglong2 p23 = *(const ulonglong2*)(wr + 2);   // (w2,w2),(w3,w3)
            unsigned long long p4 = wr[4];                   // (w4,w4)
            asm("fma.rn.f32x2 %0, %1, %2, %0;" : "+l"(acc[a]) : "l"(hv[0]), "l"(p01.x));
            asm("fma.rn.f32x2 %0, %1, %2, %0;" : "+l"(acc[a]) : "l"(hv[1]), "l"(p01.y));
            asm("fma.rn.f32x2 %0, %1, %2, %0;" : "+l"(acc[a]) : "l"(hv[2]), "l"(p23.x));
            asm("fma.rn.f32x2 %0, %1, %2, %0;" : "+l"(acc[a]) : "l"(hv[3]), "l"(p23.y));
            asm("fma.rn.f32x2 %0, %1, %2, %0;" : "+l"(acc[a]) : "l"(hv[4]), "l"(p4));
        }
    }

    // partial squared-norm per output (this chunk's 64 channels)
    #pragma unroll
    for (int a = 0; a < 8; a++) {
        float x0, y0;
        asm("mov.b64 {%0,%1}, %2;" : "=f"(x0), "=f"(y0) : "l"(acc[a]));
        float ss = x0*x0 + y0*y0;
        #pragma unroll
        for (int o = 16; o; o >>= 1) ss += __shfl_xor_sync(0xffffffffu, ss, o);
        if (lane == 0) sred[chunk][c][a] = ss;
    }
    __syncthreads();

    #pragma unroll
    for (int a = 0; a < 8; a++) {
        float tot = sred[0][c][a] + sred[1][c][a];
        float inv = 1.f / (sqrtf(tot) + EPSF);
        float x0, y0;
        asm("mov.b64 {%0,%1}, %2;" : "=f"(x0), "=f"(y0) : "l"(acc[a]));
        float* po = hob + ((size_t)(((ti0 + a) << 7) | (tj0 + c)) << 7);
        ((float2*)po)[chunk*32 + lane] = make_float2(x0*inv, y0*inv);
    }
}

// ---------------- mask head: h @ w_mask, softmax over M, NCHW out -----------
__global__ void masks_k(const float* __restrict__ wm, float* __restrict__ out) {
    __shared__ float swm[QQ*MM];
    for (int t = threadIdx.x; t < QQ*MM; t += 256) swm[t] = wm[t];
    __syncthreads();

    int gid = blockIdx.x * 256 + threadIdx.x;   // [0, B*N)
    int b = gid >> 14, p = gid & (NN-1);
    const float* hr = g_hB + (size_t)gid * QQ;  // 32 iterations -> final in hB

    float lg[MM];
    #pragma unroll
    for (int m = 0; m < MM; m++) lg[m] = 0.f;
    for (int q = 0; q < QQ; q++) {
        float hv = hr[q];
        #pragma unroll
        for (int m = 0; m < MM; m++) lg[m] += hv * swm[q*MM + m];
    }
    float mx = lg[0];
    #pragma unroll
    for (int m = 1; m < MM; m++) mx = fmaxf(mx, lg[m]);
    float s = 0.f;
    #pragma unroll
    for (int m = 0; m < MM; m++) { lg[m] = __expf(lg[m] - mx); s += lg[m]; }
    float r = 1.f / s;
    #pragma unroll
    for (int m = 0; m < MM; m++)
        out[(((size_t)(b*MM + m)) << 14) + p] = lg[m] * r;
}

// ---------------- launch ----------------------------------------------------
extern "C" void kernel_launch(void* const* d_in, const int* in_sizes, int n_in,
                              void* d_out, int out_size) {
    const float* x    = (const float*)d_in[0];
    // d_in[1] = edges (int32) — edge structure is analytic, unused
    const float* wc1  = (const float*)d_in[2];
    const float* bc1  = (const float*)d_in[3];
    const float* wc2  = (const float*)d_in[4];
    const float* bc2  = (const float*)d_in[5];
    const float* wk   = (const float*)d_in[6];
    const float* bk   = (const float*)d_in[7];
    const float* wq   = (const float*)d_in[8];
    const float* init = (const float*)d_in[9];
    const float* wm   = (const float*)d_in[10];
    float* out = (float*)d_out;

    conv1_k  <<<BB*NN*32/512, 512>>>(x, wc1, bc1);
    conv2kq_k<<<BB*NN*32/512, 512>>>(wc2, bc2, wk, bk, wq);
    edgew_k  <<<dim3(WW/8, HH/8, BB), 256>>>();

    for (int it = 0; it < 32; it++) {
        prop_k<<<dim3(WW/8, HH/8, BB), 512>>>(init, it);
    }
    masks_k<<<BB*NN/256, 256>>>(wm, out);
}

// round 10
// speedup vs baseline: 1.3179x; 1.3179x over previous
#include <cuda_runtime.h>
#include <math.h>

#define HH 128
#define WW 128
#define NN 16384          // H*W
#define BB 2
#define DD 32
#define QQ 128
#define MM 16
#define EPSF 1e-8f

#define N_ITERS 32
#define GRID_BLOCKS 512   // 16 x 16 x 2, all co-resident (<= 148*4)
#define NGROUPS 32
#define GSZ (GRID_BLOCKS/NGROUPS)   // 16

// ---------------- scratch (static device allocations; no cudaMalloc) --------
__device__ float g_feat1[BB*NN*DD];
__device__ float g_k   [BB*NN*DD];   // pre-normalized k-hat
__device__ float g_q   [BB*NN*DD];   // pre-normalized q-hat
__device__ float g_w   [BB*NN*25];   // unnormalized exp(cos) weights
__device__ float g_hA  [BB*NN*QQ];
__device__ float g_hB  [BB*NN*QQ];

// persistent-barrier state (never reset; modulo-round + gen-snapshot logic
// makes it correct across graph replays)
__device__ unsigned g_grpcnt[NGROUPS*32];   // 128B-padded counters
__device__ unsigned g_l2cnt;
__device__ unsigned g_gen;

// ---------------- conv1: (B,H,W,3) -> relu -> (B,H,W,32) --------------------
__global__ void conv1_k(const float* __restrict__ x,
                        const float* __restrict__ w,
                        const float* __restrict__ bias) {
    __shared__ float sw[3*3*3*32];
    __shared__ float sb[32];
    for (int t = threadIdx.x; t < 864; t += 512) sw[t] = w[t];
    if (threadIdx.x < 32) sb[threadIdx.x] = bias[threadIdx.x];
    __syncthreads();

    int gid = blockIdx.x * 16 + (threadIdx.x >> 5);
    int co  = threadIdx.x & 31;
    int b = gid >> 14, p = gid & (NN-1);
    int i = p >> 7, j = p & 127;

    float acc = sb[co];
    #pragma unroll
    for (int ky = 0; ky < 3; ky++) {
        int yi = i + ky - 1;
        if ((unsigned)yi >= HH) continue;
        #pragma unroll
        for (int kx = 0; kx < 3; kx++) {
            int xj = j + kx - 1;
            if ((unsigned)xj >= WW) continue;
            const float* xp = x + ((size_t)((b << 14) | (yi << 7) | xj)) * 3;
            const float* wp = sw + (ky*3 + kx) * 3 * 32;
            #pragma unroll
            for (int ci = 0; ci < 3; ci++) acc += xp[ci] * wp[ci*32 + co];
        }
    }
    g_feat1[(size_t)gid*32 + co] = fmaxf(acc, 0.f);
}

// ------- conv2 + fused k/q projection + normalization (k-hat, q-hat) --------
__global__ void conv2kq_k(const float* __restrict__ w,
                          const float* __restrict__ bias,
                          const float* __restrict__ wk,
                          const float* __restrict__ bk,
                          const float* __restrict__ wq) {
    __shared__ float sw[3*3*32*32];
    __shared__ float swk[1024], swq[1024];
    __shared__ float sb[32], sbk[32];
    for (int t = threadIdx.x; t < 9216; t += 512) sw[t] = w[t];
    for (int t = threadIdx.x; t < 1024; t += 512) { swk[t] = wk[t]; swq[t] = wq[t]; }
    if (threadIdx.x < 32) { sb[threadIdx.x] = bias[threadIdx.x]; sbk[threadIdx.x] = bk[threadIdx.x]; }
    __syncthreads();

    int gid = blockIdx.x * 16 + (threadIdx.x >> 5);
    int co  = threadIdx.x & 31;
    int b = gid >> 14, p = gid & (NN-1);
    int i = p >> 7, j = p & 127;

    float acc = sb[co];
    #pragma unroll
    for (int ky = 0; ky < 3; ky++) {
        int yi = i + ky - 1;
        if ((unsigned)yi >= HH) continue;
        #pragma unroll
        for (int kx = 0; kx < 3; kx++) {
            int xj = j + kx - 1;
            if ((unsigned)xj >= WW) continue;
            const float* fin = g_feat1 + ((size_t)((b << 14) | (yi << 7) | xj)) * 32;
            const float* wp  = sw + (ky*3 + kx) * 32 * 32;
            #pragma unroll
            for (int ci = 0; ci < 32; ci++) acc += fin[ci] * wp[ci*32 + co];
        }
    }
    float fv = fmaxf(acc, 0.f);

    float ka = sbk[co], qa = 0.f;
    #pragma unroll
    for (int ci = 0; ci < 32; ci++) {
        float f = __shfl_sync(0xffffffffu, fv, ci);
        ka += f * swk[ci*32 + co];
        qa += f * swq[ci*32 + co];
    }
    float ks = ka*ka, qs = qa*qa;
    #pragma unroll
    for (int o = 16; o; o >>= 1) {
        ks += __shfl_xor_sync(0xffffffffu, ks, o);
        qs += __shfl_xor_sync(0xffffffffu, qs, o);
    }
    float kinv = rsqrtf(fmaxf(ks, 1e-30f));
    float qinv = rsqrtf(fmaxf(qs, 1e-30f));
    g_k[(size_t)gid*32 + co] = ka * kinv;
    g_q[(size_t)gid*32 + co] = qa * qinv;
}

// ---------------- edge weights: exp(dot(q-hat, k-hat)), tile-based ----------
__global__ void edgew_k() {
    __shared__ float sk[32*145];
    __shared__ float sq[64*32];

    int b = blockIdx.z;
    int ti0 = blockIdx.y << 3, tj0 = blockIdx.x << 3;
    int tid = threadIdx.x;
    size_t bbase = (size_t)b << 14;

    for (int t = tid; t < 1152; t += 256) {
        int hp = t >> 3, c4 = t & 7;
        int hr = hp / 12, hc = hp - hr*12;
        int gi = min(max(ti0 + hr - 2, 0), HH-1);
        int gj = min(max(tj0 + hc - 2, 0), WW-1);
        float4 v = ((const float4*)(g_k + (bbase + (gi << 7) + gj) * 32))[c4];
        sk[(c4*4+0)*145 + hp] = v.x;
        sk[(c4*4+1)*145 + hp] = v.y;
        sk[(c4*4+2)*145 + hp] = v.z;
        sk[(c4*4+3)*145 + hp] = v.w;
    }
    for (int t = tid; t < 512; t += 256) {
        int p = t >> 3, c4 = t & 7;
        int gi = ti0 + (p >> 3), gj = tj0 + (p & 7);
        ((float4*)sq)[t] = ((const float4*)(g_q + (bbase + (gi << 7) + gj) * 32))[c4];
    }
    __syncthreads();

    int lane = tid & 31, a = tid >> 5;
    int d = min(lane, 24);
    int dr = d / 5, dc = d - dr*5;

    for (int cc = 0; cc < 8; cc++) {
        int p = a*8 + cc;
        int hidx = (a + dr)*12 + (cc + dc);
        const float* skp = sk + hidx;
        const float* sqp = sq + p*32;
        float s = 0.f;
        #pragma unroll
        for (int c = 0; c < 32; c++) s += sqp[c] * skp[c*145];
        if (lane < 25) {
            size_t gp = bbase + ((ti0 + a) << 7) + (tj0 + cc);
            g_w[gp*25 + lane] = __expf(s);
        }
    }
}

// ---------------- persistent propagation: 32 iters, software grid barrier ---
// R8's measured-best inner loop (256 thr, warp = tile column, lane = channel
// pair, two 64-ch chunks as in-warp ILP, (w,w)-dup weights in smem, direct
// LDG.64 halo reads). Weights staged ONCE; between iterations a two-level
// atomic grid barrier (+fences for visibility & L1 invalidation).
#define PROP_W_F2 (64*32)
__global__ __launch_bounds__(256, 4) void prop_pers_k(const float* __restrict__ hinit) {
    __shared__ float2 shw[PROP_W_F2];                // 16 KB, persists all iters
    __shared__ unsigned sgen0;

    int b = blockIdx.z;
    int ti0 = blockIdx.y << 3, tj0 = blockIdx.x << 3;
    int tid = threadIdx.x;
    int lane = tid & 31, c = tid >> 5;               // warp = tile column
    unsigned grp = (blockIdx.x + (blockIdx.y << 4) + (blockIdx.z << 8)) & (NGROUPS-1);

    if (tid == 0) sgen0 = *(volatile unsigned*)&g_gen;   // safe: gen can't
    // advance this launch until THIS block arrives at barrier 1.

    // stage weights once: (w,w) pairs; per-op row r at f2 offset op*32 + r*6
    const float* wb = g_w + ((size_t)b << 14) * 25;
    for (int t = tid; t < 1600; t += 256) {
        int op = t / 25, d = t - op*25;
        int a = op >> 3, cc = op & 7;
        int r = d / 5, cl = d - r*5;
        float ww = wb[(size_t)(((ti0 + a) << 7) | (tj0 + cc)) * 25 + d];
        shw[op*32 + r*6 + cl] = make_float2(ww, ww);
    }
    __syncthreads();
    unsigned gen0 = sgen0;

    const unsigned long long* shw64 = (const unsigned long long*)shw;

    #pragma unroll 1
    for (int it = 0; it < N_ITERS; it++) {
        const float* hin = (it & 1) ? g_hA : (it == 0 ? hinit : g_hB);
        float*       hout = (it & 1) ? g_hB : g_hA;
        const float* hb = hin + ((size_t)b << 21);
        float* hob = hout + ((size_t)b << 21);

        unsigned long long acc[2][8];
        #pragma unroll
        for (int ch = 0; ch < 2; ch++)
            #pragma unroll
            for (int a = 0; a < 8; a++) acc[ch][a] = 0ull;

        #pragma unroll
        for (int chunk = 0; chunk < 2; chunk++) {
            const float* hcb = hb + chunk*64 + 2*lane;
            #pragma unroll
            for (int hr = 0; hr < 12; hr++) {
                int gi = min(max(ti0 + hr - 2, 0), HH-1);
                const float* rowp = hcb + ((size_t)gi << 14);
                unsigned long long hv[5];
                #pragma unroll
                for (int dj = 0; dj < 5; dj++) {
                    int gj = min(max(tj0 + c + dj - 2, 0), WW-1);
                    hv[dj] = *(const unsigned long long*)(rowp + ((size_t)gj << 7));
                }
                #pragma unroll
                for (int a = 0; a < 8; a++) {
                    if (a > hr || a + 4 < hr) continue;
                    const unsigned long long* wr = shw64 + (a*8 + c)*32 + (hr - a)*6;
                    ulonglong2 p01 = *(const ulonglong2*)(wr);
                    ulonglong2 p23 = *(const ulonglong2*)(wr + 2);
                    unsigned long long p4 = wr[4];
                    asm("fma.rn.f32x2 %0, %1, %2, %0;" : "+l"(acc[chunk][a]) : "l"(hv[0]), "l"(p01.x));
                    asm("fma.rn.f32x2 %0, %1, %2, %0;" : "+l"(acc[chunk][a]) : "l"(hv[1]), "l"(p01.y));
                    asm("fma.rn.f32x2 %0, %1, %2, %0;" : "+l"(acc[chunk][a]) : "l"(hv[2]), "l"(p23.x));
                    asm("fma.rn.f32x2 %0, %1, %2, %0;" : "+l"(acc[chunk][a]) : "l"(hv[3]), "l"(p23.y));
                    asm("fma.rn.f32x2 %0, %1, %2, %0;" : "+l"(acc[chunk][a]) : "l"(hv[4]), "l"(p4));
                }
            }
        }

        #pragma unroll
        for (int a = 0; a < 8; a++) {
            float x0, y0, x1, y1;
            asm("mov.b64 {%0,%1}, %2;" : "=f"(x0), "=f"(y0) : "l"(acc[0][a]));
            asm("mov.b64 {%0,%1}, %2;" : "=f"(x1), "=f"(y1) : "l"(acc[1][a]));
            float ss = x0*x0 + y0*y0 + x1*x1 + y1*y1;
            #pragma unroll
            for (int o = 16; o; o >>= 1) ss += __shfl_xor_sync(0xffffffffu, ss, o);
            float inv = 1.f / (sqrtf(ss) + EPSF);
            float* po = hob + ((size_t)(((ti0 + a) << 7) | (tj0 + c)) << 7);
            ((float2*)po)[lane]      = make_float2(x0*inv, y0*inv);
            ((float2*)po)[32 + lane] = make_float2(x1*inv, y1*inv);
        }

        if (it != N_ITERS-1) {
            __threadfence();                 // make this iter's STGs visible
            __syncthreads();
            if (tid == 0) {
                unsigned target = gen0 + (unsigned)(it + 1);
                unsigned a = atomicAdd(&g_grpcnt[grp*32], 1u);
                if (((a + 1) & (GSZ-1)) == 0) {              // group complete
                    unsigned l2 = atomicAdd(&g_l2cnt, 1u);
                    if (((l2 + 1) & (NGROUPS-1)) == 0) {     // all groups
                        __threadfence();
                        atomicAdd(&g_gen, 1u);
                    }
                }
                while ((int)(*(volatile unsigned*)&g_gen - target) < 0)
                    __nanosleep(64);
                __threadfence();             // acquire + L1D invalidate
            }
            __syncthreads();
        }
    }
}

// ---------------- mask head: h @ w_mask, softmax over M, NCHW out -----------
__global__ void masks_k(const float* __restrict__ wm, float* __restrict__ out) {
    __shared__ float swm[QQ*MM];
    for (int t = threadIdx.x; t < QQ*MM; t += 256) swm[t] = wm[t];
    __syncthreads();

    int gid = blockIdx.x * 256 + threadIdx.x;
    int b = gid >> 14, p = gid & (NN-1);
    const float* hr = g_hB + (size_t)gid * QQ;  // it=31 (odd) wrote hB

    float lg[MM];
    #pragma unroll
    for (int m = 0; m < MM; m++) lg[m] = 0.f;
    for (int q = 0; q < QQ; q++) {
        float hv = hr[q];
        #pragma unroll
        for (int m = 0; m < MM; m++) lg[m] += hv * swm[q*MM + m];
    }
    float mx = lg[0];
    #pragma unroll
    for (int m = 1; m < MM; m++) mx = fmaxf(mx, lg[m]);
    float s = 0.f;
    #pragma unroll
    for (int m = 0; m < MM; m++) { lg[m] = __expf(lg[m] - mx); s += lg[m]; }
    float r = 1.f / s;
    #pragma unroll
    for (int m = 0; m < MM; m++)
        out[(((size_t)(b*MM + m)) << 14) + p] = lg[m] * r;
}

// ---------------- launch ----------------------------------------------------
extern "C" void kernel_launch(void* const* d_in, const int* in_sizes, int n_in,
                              void* d_out, int out_size) {
    const float* x    = (const float*)d_in[0];
    // d_in[1] = edges (int32) — edge structure is analytic, unused
    const float* wc1  = (const float*)d_in[2];
    const float* bc1  = (const float*)d_in[3];
    const float* wc2  = (const float*)d_in[4];
    const float* bc2  = (const float*)d_in[5];
    const float* wk   = (const float*)d_in[6];
    const float* bk   = (const float*)d_in[7];
    const float* wq   = (const float*)d_in[8];
    const float* init = (const float*)d_in[9];
    const float* wm   = (const float*)d_in[10];
    float* out = (float*)d_out;

    conv1_k  <<<BB*NN*32/512, 512>>>(x, wc1, bc1);
    conv2kq_k<<<BB*NN*32/512, 512>>>(wc2, bc2, wk, bk, wq);
    edgew_k  <<<dim3(WW/8, HH/8, BB), 256>>>();
    prop_pers_k<<<dim3(WW/8, HH/8, BB), 256>>>(init);
    masks_k  <<<BB*NN/256, 256>>>(wm, out);
}

// round 11
// speedup vs baseline: 1.3593x; 1.0314x over previous
#include <cuda_runtime.h>
#include <math.h>

#define HH 128
#define WW 128
#define NN 16384          // H*W
#define BB 2
#define DD 32
#define QQ 128
#define MM 16
#define EPSF 1e-8f

// ---------------- scratch (static device allocations; no cudaMalloc) --------
__device__ float g_feat1[BB*NN*DD];
__device__ float g_k   [BB*NN*DD];   // pre-normalized k-hat
__device__ float g_q   [BB*NN*DD];   // pre-normalized q-hat
__device__ float g_w   [BB*NN*25];   // unnormalized exp(cos) weights
__device__ float g_hA  [BB*NN*QQ];
__device__ float g_hB  [BB*NN*QQ];

// ---------------- conv1: (B,H,W,3) -> relu -> (B,H,W,32) --------------------
__global__ void conv1_k(const float* __restrict__ x,
                        const float* __restrict__ w,
                        const float* __restrict__ bias) {
    __shared__ float sw[3*3*3*32];
    __shared__ float sb[32];
    for (int t = threadIdx.x; t < 864; t += 512) sw[t] = w[t];
    if (threadIdx.x < 32) sb[threadIdx.x] = bias[threadIdx.x];
    __syncthreads();

    int gid = blockIdx.x * 16 + (threadIdx.x >> 5);   // pixel in [0, B*N)
    int co  = threadIdx.x & 31;
    int b = gid >> 14, p = gid & (NN-1);
    int i = p >> 7, j = p & 127;

    float acc = sb[co];
    #pragma unroll
    for (int ky = 0; ky < 3; ky++) {
        int yi = i + ky - 1;
        if ((unsigned)yi >= HH) continue;
        #pragma unroll
        for (int kx = 0; kx < 3; kx++) {
            int xj = j + kx - 1;
            if ((unsigned)xj >= WW) continue;
            const float* xp = x + ((size_t)((b << 14) | (yi << 7) | xj)) * 3;
            const float* wp = sw + (ky*3 + kx) * 3 * 32;
            #pragma unroll
            for (int ci = 0; ci < 3; ci++) acc += xp[ci] * wp[ci*32 + co];
        }
    }
    g_feat1[(size_t)gid*32 + co] = fmaxf(acc, 0.f);
}

// ------- conv2 + fused k/q projection + normalization (k-hat, q-hat) --------
__global__ void conv2kq_k(const float* __restrict__ w,
                          const float* __restrict__ bias,
                          const float* __restrict__ wk,
                          const float* __restrict__ bk,
                          const float* __restrict__ wq) {
    __shared__ float sw[3*3*32*32];
    __shared__ float swk[1024], swq[1024];
    __shared__ float sb[32], sbk[32];
    for (int t = threadIdx.x; t < 9216; t += 512) sw[t] = w[t];
    for (int t = threadIdx.x; t < 1024; t += 512) { swk[t] = wk[t]; swq[t] = wq[t]; }
    if (threadIdx.x < 32) { sb[threadIdx.x] = bias[threadIdx.x]; sbk[threadIdx.x] = bk[threadIdx.x]; }
    __syncthreads();

    int gid = blockIdx.x * 16 + (threadIdx.x >> 5);
    int co  = threadIdx.x & 31;
    int b = gid >> 14, p = gid & (NN-1);
    int i = p >> 7, j = p & 127;

    float acc = sb[co];
    #pragma unroll
    for (int ky = 0; ky < 3; ky++) {
        int yi = i + ky - 1;
        if ((unsigned)yi >= HH) continue;
        #pragma unroll
        for (int kx = 0; kx < 3; kx++) {
            int xj = j + kx - 1;
            if ((unsigned)xj >= WW) continue;
            const float* fin = g_feat1 + ((size_t)((b << 14) | (yi << 7) | xj)) * 32;
            const float* wp  = sw + (ky*3 + kx) * 32 * 32;
            #pragma unroll
            for (int ci = 0; ci < 32; ci++) acc += fin[ci] * wp[ci*32 + co];
        }
    }
    float fv = fmaxf(acc, 0.f);

    float ka = sbk[co], qa = 0.f;
    #pragma unroll
    for (int ci = 0; ci < 32; ci++) {
        float f = __shfl_sync(0xffffffffu, fv, ci);
        ka += f * swk[ci*32 + co];
        qa += f * swq[ci*32 + co];
    }
    float ks = ka*ka, qs = qa*qa;
    #pragma unroll
    for (int o = 16; o; o >>= 1) {
        ks += __shfl_xor_sync(0xffffffffu, ks, o);
        qs += __shfl_xor_sync(0xffffffffu, qs, o);
    }
    float kinv = rsqrtf(fmaxf(ks, 1e-30f));
    float qinv = rsqrtf(fmaxf(qs, 1e-30f));
    g_k[(size_t)gid*32 + co] = ka * kinv;
    g_q[(size_t)gid*32 + co] = qa * qinv;
}

// ---------------- edge weights: exp(dot(q-hat, k-hat)), tile-based ----------
__global__ void edgew_k() {
    __shared__ float sk[32*145];
    __shared__ float sq[64*32];

    int b = blockIdx.z;
    int ti0 = blockIdx.y << 3, tj0 = blockIdx.x << 3;
    int tid = threadIdx.x;
    size_t bbase = (size_t)b << 14;

    for (int t = tid; t < 1152; t += 256) {
        int hp = t >> 3, c4 = t & 7;
        int hr = hp / 12, hc = hp - hr*12;
        int gi = min(max(ti0 + hr - 2, 0), HH-1);
        int gj = min(max(tj0 + hc - 2, 0), WW-1);
        float4 v = ((const float4*)(g_k + (bbase + (gi << 7) + gj) * 32))[c4];
        sk[(c4*4+0)*145 + hp] = v.x;
        sk[(c4*4+1)*145 + hp] = v.y;
        sk[(c4*4+2)*145 + hp] = v.z;
        sk[(c4*4+3)*145 + hp] = v.w;
    }
    for (int t = tid; t < 512; t += 256) {
        int p = t >> 3, c4 = t & 7;
        int gi = ti0 + (p >> 3), gj = tj0 + (p & 7);
        ((float4*)sq)[t] = ((const float4*)(g_q + (bbase + (gi << 7) + gj) * 32))[c4];
    }
    __syncthreads();

    int lane = tid & 31, a = tid >> 5;
    int d = min(lane, 24);
    int dr = d / 5, dc = d - dr*5;

    for (int cc = 0; cc < 8; cc++) {
        int p = a*8 + cc;
        int hidx = (a + dr)*12 + (cc + dc);
        const float* skp = sk + hidx;
        const float* sqp = sq + p*32;
        float s = 0.f;
        #pragma unroll
        for (int c = 0; c < 32; c++) s += sqp[c] * skp[c*145];
        if (lane < 25) {
            size_t gp = bbase + ((ti0 + a) << 7) + (tj0 + cc);
            g_w[gp*25 + lane] = __expf(s);
        }
    }
}

// ---------------- propagation: weighted 5x5 stencil + L2-normalize ----------
// 8x8 tile / block, 256 threads, warp = tile column, lane = channel pair.
// hr-OUTER loop: both 64-ch chunks' halo values loaded per row (10x LDG.64,
// direct from global, L1-served reuse, no halo smem / no barriers), then each
// weight row is fetched ONCE (2x LDS.128 + 1x LDS.64) and applied to BOTH
// chunks (10x fma.rn.f32x2) -- halves weight-LDS vs chunk-outer. Column
// clamps hoisted out of the row loop.
#define PROP_W_F2 (64*32)     // 64 ops x 32 float2 (row stride 6, padded)
__global__ __launch_bounds__(256, 4) void prop_k(const float* __restrict__ hinit, int it) {
    __shared__ float2 shw[PROP_W_F2];                // 16 KB

    const float* hin = (it == 0) ? hinit : ((it & 1) ? g_hA : g_hB);
    float*       hout = (it & 1) ? g_hB : g_hA;

    int b = blockIdx.z;
    int ti0 = blockIdx.y << 3, tj0 = blockIdx.x << 3;
    int tid = threadIdx.x;
    int lane = tid & 31, c = tid >> 5;               // warp = tile column

    const float* hb = hin + ((size_t)b << 21);       // b*N*128
    float* hob = hout + ((size_t)b << 21);

    // stage weights: (w,w) pairs; per-op row r at float2 offset op*32 + r*6
    const float* wb = g_w + ((size_t)b << 14) * 25;
    for (int t = tid; t < 1600; t += 256) {
        int op = t / 25, d = t - op*25;
        int a = op >> 3, cc = op & 7;
        int r = d / 5, cl = d - r*5;
        float ww = wb[(size_t)(((ti0 + a) << 7) | (tj0 + cc)) * 25 + d];
        shw[op*32 + r*6 + cl] = make_float2(ww, ww);
    }
    __syncthreads();

    const unsigned long long* shw64 = (const unsigned long long*)shw;

    // hr-invariant column element-offsets (floats) for this warp's 5 taps
    unsigned cOff[5];
    #pragma unroll
    for (int dj = 0; dj < 5; dj++) {
        int gj = min(max(tj0 + c + dj - 2, 0), WW-1);
        cOff[dj] = (unsigned)gj << 7;
    }
    const float* hpl = hb + 2*lane;                  // lane's channel pair base

    unsigned long long acc0[8], acc1[8];
    #pragma unroll
    for (int a = 0; a < 8; a++) { acc0[a] = 0ull; acc1[a] = 0ull; }

    #pragma unroll
    for (int hr = 0; hr < 12; hr++) {
        int gi = min(max(ti0 + hr - 2, 0), HH-1);
        const float* rowp = hpl + ((size_t)gi << 14);
        unsigned long long h0[5], h1[5];
        #pragma unroll
        for (int dj = 0; dj < 5; dj++) {
            h0[dj] = *(const unsigned long long*)(rowp + cOff[dj]);
            h1[dj] = *(const unsigned long long*)(rowp + cOff[dj] + 64);
        }
        #pragma unroll
        for (int a = 0; a < 8; a++) {
            if (a > hr || a + 4 < hr) continue;          // compile-time pruned
            const unsigned long long* wr = shw64 + (a*8 + c)*32 + (hr - a)*6;
            ulonglong2 p01 = *(const ulonglong2*)(wr);   // (w0,w0),(w1,w1)
            ulonglong2 p23 = *(const ulonglong2*)(wr + 2);
            unsigned long long p4 = wr[4];
            asm("fma.rn.f32x2 %0, %1, %2, %0;" : "+l"(acc0[a]) : "l"(h0[0]), "l"(p01.x));
            asm("fma.rn.f32x2 %0, %1, %2, %0;" : "+l"(acc1[a]) : "l"(h1[0]), "l"(p01.x));
            asm("fma.rn.f32x2 %0, %1, %2, %0;" : "+l"(acc0[a]) : "l"(h0[1]), "l"(p01.y));
            asm("fma.rn.f32x2 %0, %1, %2, %0;" : "+l"(acc1[a]) : "l"(h1[1]), "l"(p01.y));
            asm("fma.rn.f32x2 %0, %1, %2, %0;" : "+l"(acc0[a]) : "l"(h0[2]), "l"(p23.x));
            asm("fma.rn.f32x2 %0, %1, %2, %0;" : "+l"(acc1[a]) : "l"(h1[2]), "l"(p23.x));
            asm("fma.rn.f32x2 %0, %1, %2, %0;" : "+l"(acc0[a]) : "l"(h0[3]), "l"(p23.y));
            asm("fma.rn.f32x2 %0, %1, %2, %0;" : "+l"(acc1[a]) : "l"(h1[3]), "l"(p23.y));
            asm("fma.rn.f32x2 %0, %1, %2, %0;" : "+l"(acc0[a]) : "l"(h0[4]), "l"(p4));
            asm("fma.rn.f32x2 %0, %1, %2, %0;" : "+l"(acc1[a]) : "l"(h1[4]), "l"(p4));
        }
    }

    #pragma unroll
    for (int a = 0; a < 8; a++) {
        float x0, y0, x1, y1;
        asm("mov.b64 {%0,%1}, %2;" : "=f"(x0), "=f"(y0) : "l"(acc0[a]));
        asm("mov.b64 {%0,%1}, %2;" : "=f"(x1), "=f"(y1) : "l"(acc1[a]));
        float ss = x0*x0 + y0*y0 + x1*x1 + y1*y1;
        #pragma unroll
        for (int o = 16; o; o >>= 1) ss += __shfl_xor_sync(0xffffffffu, ss, o);
        float inv = 1.f / (sqrtf(ss) + EPSF);
        float* po = hob + ((size_t)(((ti0 + a) << 7) | (tj0 + c)) << 7);
        ((float2*)po)[lane]      = make_float2(x0*inv, y0*inv);
        ((float2*)po)[32 + lane] = make_float2(x1*inv, y1*inv);
    }
}

// ---------------- mask head: h @ w_mask, softmax over M, NCHW out -----------
__global__ void masks_k(const float* __restrict__ wm, float* __restrict__ out) {
    __shared__ float swm[QQ*MM];
    for (int t = threadIdx.x; t < QQ*MM; t += 256) swm[t] = wm[t];
    __syncthreads();

    int gid = blockIdx.x * 256 + threadIdx.x;
    int b = gid >> 14, p = gid & (NN-1);
    const float* hr = g_hB + (size_t)gid * QQ;  // it=31 (odd) wrote hB

    float lg[MM];
    #pragma unroll
    for (int m = 0; m < MM; m++) lg[m] = 0.f;
    for (int q = 0; q < QQ; q++) {
        float hv = hr[q];
        #pragma unroll
        for (int m = 0; m < MM; m++) lg[m] += hv * swm[q*MM + m];
    }
    float mx = lg[0];
    #pragma unroll
    for (int m = 1; m < MM; m++) mx = fmaxf(mx, lg[m]);
    float s = 0.f;
    #pragma unroll
    for (int m = 0; m < MM; m++) { lg[m] = __expf(lg[m] - mx); s += lg[m]; }
    float r = 1.f / s;
    #pragma unroll
    for (int m = 0; m < MM; m++)
        out[(((size_t)(b*MM + m)) << 14) + p] = lg[m] * r;
}

// ---------------- launch ----------------------------------------------------
extern "C" void kernel_launch(void* const* d_in, const int* in_sizes, int n_in,
                              void* d_out, int out_size) {
    const float* x    = (const float*)d_in[0];
    // d_in[1] = edges (int32) — edge structure is analytic, unused
    const float* wc1  = (const float*)d_in[2];
    const float* bc1  = (const float*)d_in[3];
    const float* wc2  = (const float*)d_in[4];
    const float* bc2  = (const float*)d_in[5];
    const float* wk   = (const float*)d_in[6];
    const float* bk   = (const float*)d_in[7];
    const float* wq   = (const float*)d_in[8];
    const float* init = (const float*)d_in[9];
    const float* wm   = (const float*)d_in[10];
    float* out = (float*)d_out;

    conv1_k  <<<BB*NN*32/512, 512>>>(x, wc1, bc1);
    conv2kq_k<<<BB*NN*32/512, 512>>>(wc2, bc2, wk, bk, wq);
    edgew_k  <<<dim3(WW/8, HH/8, BB), 256>>>();

    for (int it = 0; it < 32; it++) {
        prop_k<<<dim3(WW/8, HH/8, BB), 256>>>(init, it);
    }
    masks_k<<<BB*NN/256, 256>>>(wm, out);
}

// round 12
// speedup vs baseline: 1.3733x; 1.0103x over previous
#include <cuda_runtime.h>
#include <math.h>

#define HH 128
#define WW 128
#define NN 16384          // H*W
#define BB 2
#define DD 32
#define QQ 128
#define MM 16
#define EPSF 1e-8f

// ---------------- scratch (static device allocations; no cudaMalloc) --------
__device__ float g_feat1[BB*NN*DD];
__device__ float g_k   [BB*NN*DD];   // pre-normalized k-hat
__device__ float g_q   [BB*NN*DD];   // pre-normalized q-hat
__device__ float g_w   [BB*NN*25];   // unnormalized exp(cos) weights
__device__ float g_hA  [BB*NN*QQ];
__device__ float g_hB  [BB*NN*QQ];

// ---------------- conv1: (B,H,W,3) -> relu -> (B,H,W,32) --------------------
// 512 threads, each warp processes 4 pixels: weights staged once per 64 px.
__global__ __launch_bounds__(512) void conv1_k(const float* __restrict__ x,
                        const float* __restrict__ w,
                        const float* __restrict__ bias) {
    __shared__ float sw[3*3*3*32];
    __shared__ float sb[32];
    for (int t = threadIdx.x; t < 864; t += 512) sw[t] = w[t];
    if (threadIdx.x < 32) sb[threadIdx.x] = bias[threadIdx.x];
    __syncthreads();

    int warp = threadIdx.x >> 5;
    int co   = threadIdx.x & 31;

    #pragma unroll
    for (int ii = 0; ii < 4; ii++) {
        int gid = blockIdx.x * 64 + ii*16 + warp;    // pixel in [0, B*N)
        int b = gid >> 14, p = gid & (NN-1);
        int i = p >> 7, j = p & 127;

        float acc = sb[co];
        #pragma unroll
        for (int ky = 0; ky < 3; ky++) {
            int yi = i + ky - 1;
            if ((unsigned)yi >= HH) continue;
            #pragma unroll
            for (int kx = 0; kx < 3; kx++) {
                int xj = j + kx - 1;
                if ((unsigned)xj >= WW) continue;
                const float* xp = x + ((size_t)((b << 14) | (yi << 7) | xj)) * 3;
                const float* wp = sw + (ky*3 + kx) * 3 * 32;
                #pragma unroll
                for (int ci = 0; ci < 3; ci++) acc += xp[ci] * wp[ci*32 + co];
            }
        }
        g_feat1[(size_t)gid*32 + co] = fmaxf(acc, 0.f);
    }
}

// ------- conv2 + fused k/q projection + normalization (k-hat, q-hat) --------
// 512 threads, warp loops 4 pixels: 45KB weight staging amortized over 64 px
// (was 16) -> 4x less redundant weight traffic.
__global__ __launch_bounds__(512) void conv2kq_k(const float* __restrict__ w,
                          const float* __restrict__ bias,
                          const float* __restrict__ wk,
                          const float* __restrict__ bk,
                          const float* __restrict__ wq) {
    __shared__ float sw[3*3*32*32];
    __shared__ float swk[1024], swq[1024];
    __shared__ float sb[32], sbk[32];
    for (int t = threadIdx.x; t < 9216; t += 512) sw[t] = w[t];
    for (int t = threadIdx.x; t < 1024; t += 512) { swk[t] = wk[t]; swq[t] = wq[t]; }
    if (threadIdx.x < 32) { sb[threadIdx.x] = bias[threadIdx.x]; sbk[threadIdx.x] = bk[threadIdx.x]; }
    __syncthreads();

    int warp = threadIdx.x >> 5;
    int co   = threadIdx.x & 31;

    #pragma unroll 1
    for (int ii = 0; ii < 4; ii++) {
        int gid = blockIdx.x * 64 + ii*16 + warp;
        int b = gid >> 14, p = gid & (NN-1);
        int i = p >> 7, j = p & 127;

        float acc = sb[co];
        #pragma unroll
        for (int ky = 0; ky < 3; ky++) {
            int yi = i + ky - 1;
            if ((unsigned)yi >= HH) continue;
            #pragma unroll
            for (int kx = 0; kx < 3; kx++) {
                int xj = j + kx - 1;
                if ((unsigned)xj >= WW) continue;
                const float* fin = g_feat1 + ((size_t)((b << 14) | (yi << 7) | xj)) * 32;
                const float* wp  = sw + (ky*3 + kx) * 32 * 32;
                #pragma unroll
                for (int ci = 0; ci < 32; ci++) acc += fin[ci] * wp[ci*32 + co];
            }
        }
        float fv = fmaxf(acc, 0.f);

        float ka = sbk[co], qa = 0.f;
        #pragma unroll
        for (int ci = 0; ci < 32; ci++) {
            float f = __shfl_sync(0xffffffffu, fv, ci);
            ka += f * swk[ci*32 + co];
            qa += f * swq[ci*32 + co];
        }
        float ks = ka*ka, qs = qa*qa;
        #pragma unroll
        for (int o = 16; o; o >>= 1) {
            ks += __shfl_xor_sync(0xffffffffu, ks, o);
            qs += __shfl_xor_sync(0xffffffffu, qs, o);
        }
        float kinv = rsqrtf(fmaxf(ks, 1e-30f));
        float qinv = rsqrtf(fmaxf(qs, 1e-30f));
        g_k[(size_t)gid*32 + co] = ka * kinv;
        g_q[(size_t)gid*32 + co] = qa * qinv;
    }
}

// ---------------- edge weights: exp(dot(q-hat, k-hat)), tile-based ----------
__global__ void edgew_k() {
    __shared__ float sk[32*145];
    __shared__ float sq[64*32];

    int b = blockIdx.z;
    int ti0 = blockIdx.y << 3, tj0 = blockIdx.x << 3;
    int tid = threadIdx.x;
    size_t bbase = (size_t)b << 14;

    for (int t = tid; t < 1152; t += 256) {
        int hp = t >> 3, c4 = t & 7;
        int hr = hp / 12, hc = hp - hr*12;
        int gi = min(max(ti0 + hr - 2, 0), HH-1);
        int gj = min(max(tj0 + hc - 2, 0), WW-1);
        float4 v = ((const float4*)(g_k + (bbase + (gi << 7) + gj) * 32))[c4];
        sk[(c4*4+0)*145 + hp] = v.x;
        sk[(c4*4+1)*145 + hp] = v.y;
        sk[(c4*4+2)*145 + hp] = v.z;
        sk[(c4*4+3)*145 + hp] = v.w;
    }
    for (int t = tid; t < 512; t += 256) {
        int p = t >> 3, c4 = t & 7;
        int gi = ti0 + (p >> 3), gj = tj0 + (p & 7);
        ((float4*)sq)[t] = ((const float4*)(g_q + (bbase + (gi << 7) + gj) * 32))[c4];
    }
    __syncthreads();

    int lane = tid & 31, a = tid >> 5;
    int d = min(lane, 24);
    int dr = d / 5, dc = d - dr*5;

    for (int cc = 0; cc < 8; cc++) {
        int p = a*8 + cc;
        int hidx = (a + dr)*12 + (cc + dc);
        const float* skp = sk + hidx;
        const float* sqp = sq + p*32;
        float s = 0.f;
        #pragma unroll
        for (int c = 0; c < 32; c++) s += sqp[c] * skp[c*145];
        if (lane < 25) {
            size_t gp = bbase + ((ti0 + a) << 7) + (tj0 + cc);
            g_w[gp*25 + lane] = __expf(s);
        }
    }
}

// ---------------- propagation: weighted 5x5 stencil + L2-normalize ----------
// 8x8 tile / block, 256 threads, warp = tile column, lane = FOUR adjacent
// channels (one ulonglong2 = LDG.128, 512B/warp access): 128 channels in a
// single pass -- halves LDG instruction count vs channel-pair chunks and
// doubles in-flight bytes per issued load. hr-outer, weights fetched once
// per (output,row) as 2x LDS.128 + 1x LDS.64 of (w,w) pairs, column clamps
// hoisted. Direct-global halo reads (L1-served reuse), no barriers.
#define PROP_W_F2 (64*32)     // 64 ops x 32 float2 (row stride 6, padded)
__global__ __launch_bounds__(256, 4) void prop_k(const float* __restrict__ hinit, int it) {
    __shared__ float2 shw[PROP_W_F2];                // 16 KB

    const float* hin = (it == 0) ? hinit : ((it & 1) ? g_hA : g_hB);
    float*       hout = (it & 1) ? g_hB : g_hA;

    int b = blockIdx.z;
    int ti0 = blockIdx.y << 3, tj0 = blockIdx.x << 3;
    int tid = threadIdx.x;
    int lane = tid & 31, c = tid >> 5;               // warp = tile column

    const float* hb = hin + ((size_t)b << 21);       // b*N*128
    float* hob = hout + ((size_t)b << 21);

    // stage weights: (w,w) pairs; per-op row r at float2 offset op*32 + r*6
    const float* wb = g_w + ((size_t)b << 14) * 25;
    for (int t = tid; t < 1600; t += 256) {
        int op = t / 25, d = t - op*25;
        int a = op >> 3, cc = op & 7;
        int r = d / 5, cl = d - r*5;
        float ww = wb[(size_t)(((ti0 + a) << 7) | (tj0 + cc)) * 25 + d];
        shw[op*32 + r*6 + cl] = make_float2(ww, ww);
    }
    __syncthreads();

    const unsigned long long* shw64 = (const unsigned long long*)shw;

    // hr-invariant column element-offsets (floats) for this warp's 5 taps
    unsigned cOff[5];
    #pragma unroll
    for (int dj = 0; dj < 5; dj++) {
        int gj = min(max(tj0 + c + dj - 2, 0), WW-1);
        cOff[dj] = (unsigned)gj << 7;
    }
    const float* hpl = hb + 4*lane;                  // lane's 4-channel base

    unsigned long long acc0[8], acc1[8];
    #pragma unroll
    for (int a = 0; a < 8; a++) { acc0[a] = 0ull; acc1[a] = 0ull; }

    #pragma unroll
    for (int hr = 0; hr < 12; hr++) {
        int gi = min(max(ti0 + hr - 2, 0), HH-1);
        const float* rowp = hpl + ((size_t)gi << 14);
        unsigned long long h0[5], h1[5];
        #pragma unroll
        for (int dj = 0; dj < 5; dj++) {
            ulonglong2 hv = *(const ulonglong2*)(rowp + cOff[dj]);   // LDG.128
            h0[dj] = hv.x; h1[dj] = hv.y;
        }
        #pragma unroll
        for (int a = 0; a < 8; a++) {
            if (a > hr || a + 4 < hr) continue;          // compile-time pruned
            const unsigned long long* wr = shw64 + (a*8 + c)*32 + (hr - a)*6;
            ulonglong2 p01 = *(const ulonglong2*)(wr);   // (w0,w0),(w1,w1)
            ulonglong2 p23 = *(const ulonglong2*)(wr + 2);
            unsigned long long p4 = wr[4];
            asm("fma.rn.f32x2 %0, %1, %2, %0;" : "+l"(acc0[a]) : "l"(h0[0]), "l"(p01.x));
            asm("fma.rn.f32x2 %0, %1, %2, %0;" : "+l"(acc1[a]) : "l"(h1[0]), "l"(p01.x));
            asm("fma.rn.f32x2 %0, %1, %2, %0;" : "+l"(acc0[a]) : "l"(h0[1]), "l"(p01.y));
            asm("fma.rn.f32x2 %0, %1, %2, %0;" : "+l"(acc1[a]) : "l"(h1[1]), "l"(p01.y));
            asm("fma.rn.f32x2 %0, %1, %2, %0;" : "+l"(acc0[a]) : "l"(h0[2]), "l"(p23.x));
            asm("fma.rn.f32x2 %0, %1, %2, %0;" : "+l"(acc1[a]) : "l"(h1[2]), "l"(p23.x));
            asm("fma.rn.f32x2 %0, %1, %2, %0;" : "+l"(acc0[a]) : "l"(h0[3]), "l"(p23.y));
            asm("fma.rn.f32x2 %0, %1, %2, %0;" : "+l"(acc1[a]) : "l"(h1[3]), "l"(p23.y));
            asm("fma.rn.f32x2 %0, %1, %2, %0;" : "+l"(acc0[a]) : "l"(h0[4]), "l"(p4));
            asm("fma.rn.f32x2 %0, %1, %2, %0;" : "+l"(acc1[a]) : "l"(h1[4]), "l"(p4));
        }
    }

    #pragma unroll
    for (int a = 0; a < 8; a++) {
        float x0, y0, z0, w0;
        asm("mov.b64 {%0,%1}, %2;" : "=f"(x0), "=f"(y0) : "l"(acc0[a]));
        asm("mov.b64 {%0,%1}, %2;" : "=f"(z0), "=f"(w0) : "l"(acc1[a]));
        float ss = x0*x0 + y0*y0 + z0*z0 + w0*w0;
        #pragma unroll
        for (int o = 16; o; o >>= 1) ss += __shfl_xor_sync(0xffffffffu, ss, o);
        float inv = 1.f / (sqrtf(ss) + EPSF);
        float* po = hob + ((size_t)(((ti0 + a) << 7) | (tj0 + c)) << 7);
        ((float4*)po)[lane] = make_float4(x0*inv, y0*inv, z0*inv, w0*inv);
    }
}

// ---------------- mask head: h @ w_mask, softmax over M, NCHW out -----------
__global__ void masks_k(const float* __restrict__ wm, float* __restrict__ out) {
    __shared__ float swm[QQ*MM];
    for (int t = threadIdx.x; t < QQ*MM; t += 256) swm[t] = wm[t];
    __syncthreads();

    int gid = blockIdx.x * 256 + threadIdx.x;
    int b = gid >> 14, p = gid & (NN-1);
    const float* hr = g_hB + (size_t)gid * QQ;  // it=31 (odd) wrote hB

    float lg[MM];
    #pragma unroll
    for (int m = 0; m < MM; m++) lg[m] = 0.f;
    for (int q = 0; q < QQ; q++) {
        float hv = hr[q];
        #pragma unroll
        for (int m = 0; m < MM; m++) lg[m] += hv * swm[q*MM + m];
    }
    float mx = lg[0];
    #pragma unroll
    for (int m = 1; m < MM; m++) mx = fmaxf(mx, lg[m]);
    float s = 0.f;
    #pragma unroll
    for (int m = 0; m < MM; m++) { lg[m] = __expf(lg[m] - mx); s += lg[m]; }
    float r = 1.f / s;
    #pragma unroll
    for (int m = 0; m < MM; m++)
        out[(((size_t)(b*MM + m)) << 14) + p] = lg[m] * r;
}

// ---------------- launch ----------------------------------------------------
extern "C" void kernel_launch(void* const* d_in, const int* in_sizes, int n_in,
                              void* d_out, int out_size) {
    const float* x    = (const float*)d_in[0];
    // d_in[1] = edges (int32) — edge structure is analytic, unused
    const float* wc1  = (const float*)d_in[2];
    const float* bc1  = (const float*)d_in[3];
    const float* wc2  = (const float*)d_in[4];
    const float* bc2  = (const float*)d_in[5];
    const float* wk   = (const float*)d_in[6];
    const float* bk   = (const float*)d_in[7];
    const float* wq   = (const float*)d_in[8];
    const float* init = (const float*)d_in[9];
    const float* wm   = (const float*)d_in[10];
    float* out = (float*)d_out;

    conv1_k  <<<BB*NN/64, 512>>>(x, wc1, bc1);
    conv2kq_k<<<BB*NN/64, 512>>>(wc2, bc2, wk, bk, wq);
    edgew_k  <<<dim3(WW/8, HH/8, BB), 256>>>();

    for (int it = 0; it < 32; it++) {
        prop_k<<<dim3(WW/8, HH/8, BB), 256>>>(init, it);
    }
    masks_k<<<BB*NN/256, 256>>>(wm, out);
}